// round 13
// baseline (speedup 1.0000x reference)
#include <cuda_runtime.h>
#include <math.h>

#define NQ   6
#define DIM  64
#define NWARP 12
#define NTHR (NWARP * 32)
#define SPT  (NWARP * 32)   // 384 samples per iteration per CTA (32 per warp)
#define PW   72             // weight pitch (words), half-shift layout
#define PA   416            // unified a-tile pitch: 384 cols + slack (raw cols <= 413)

typedef unsigned long long ull;

__device__ float g_CRT[DIM * DIM];   // [j][i]
__device__ float g_CIT[DIM * DIM];   // [j][i]
__device__ float g_Mz[5 * DIM];      // [o][i]
__device__ float g_W2g[NQ * DIM];    // W2[q][i] * ln_g[i]
__device__ float g_Sg[NQ];           // sum_i W2[q][i]*g[i]
__device__ float g_Cq[NQ];           // sum_i lnb[i]*W2[q][i] + b2[q]

__device__ __forceinline__ void ffma2(ull &d, ull a, ull b) {
    asm("fma.rn.f32x2 %0, %1, %2, %0;" : "+l"(d) : "l"(a), "l"(b));
}
__device__ __forceinline__ ull dup2(float v) {
    ull r; asm("mov.b64 %0, {%1, %1};" : "=l"(r) : "f"(v)); return r;
}
// half-shift: words i>=32 shifted +4 so 8 lanes at 32B stride hit distinct bank quads
__device__ __forceinline__ int ish(int i) { return i + ((i >> 5) << 2); }

__device__ __forceinline__ float fast_tanh(float x) {
    float e = __expf(-2.f * fabsf(x));
    float t = __fdividef(1.f - e, 1.f + e);
    return copysignf(t, x);
}

__device__ __forceinline__ int ring_map(int r, int i) {
    int v = i;
    for (int w = NQ - 1; w >= 0; --w) {
        int t = (w + r) % NQ;
        v ^= ((v >> (NQ - 1 - w)) & 1) << (NQ - 1 - t);
    }
    return v;
}

// One block, 64 threads. Thread j owns column j of C.
__global__ void setup_kernel(const float* __restrict__ th_sh,
                             const float* __restrict__ th_tk,
                             const float* __restrict__ Wc,
                             const float* __restrict__ W2,
                             const float* __restrict__ lng,
                             const float* __restrict__ lnb,
                             const float* __restrict__ b2) {
    __shared__ float2 C[DIM][DIM];
    int j = threadIdx.x;
    if (j >= DIM) return;
    for (int i = 0; i < DIM; i++) C[i][j] = make_float2(i == j ? 1.f : 0.f, 0.f);

    const float* TH[3] = { th_sh, th_sh + NQ * 3, th_tk };
    const int    RS[3] = { 1, 2, 1 };

    for (int l = 0; l < 3; l++) {
        const float* th = TH[l];
        for (int w = 0; w < NQ; w++) {
            float phi = th[w * 3 + 0], te = th[w * 3 + 1], om = th[w * 3 + 2];
            float sth, cth; sincosf(0.5f * te, &sth, &cth);
            float a = 0.5f * (phi + om), b = 0.5f * (phi - om);
            float sa, ca, sb, cb;
            sincosf(a, &sa, &ca);
            sincosf(b, &sb, &cb);
            float2 R00 = make_float2( ca * cth, -sa * cth);
            float2 R01 = make_float2(-cb * sth, -sb * sth);
            float2 R10 = make_float2( cb * sth, -sb * sth);
            float2 R11 = make_float2( ca * cth,  sa * cth);
            int bit = 1 << (NQ - 1 - w);
            for (int i0 = 0; i0 < DIM; i0++) {
                if (i0 & bit) continue;
                int i1 = i0 | bit;
                float2 v0 = C[i0][j], v1 = C[i1][j];
                C[i0][j] = make_float2(
                    R00.x * v0.x - R00.y * v0.y + R01.x * v1.x - R01.y * v1.y,
                    R00.x * v0.y + R00.y * v0.x + R01.x * v1.y + R01.y * v1.x);
                C[i1][j] = make_float2(
                    R10.x * v0.x - R10.y * v0.y + R11.x * v1.x - R11.y * v1.y,
                    R10.x * v0.y + R10.y * v0.x + R11.x * v1.y + R11.y * v1.x);
            }
        }
        float2 tmp[DIM];
        for (int i = 0; i < DIM; i++) tmp[i] = C[ring_map(RS[l], i)][j];
        for (int i = 0; i < DIM; i++) C[i][j] = tmp[i];
    }
    for (int i = 0; i < DIM; i++) {
        g_CRT[j * DIM + i] = C[i][j].x;
        g_CIT[j * DIM + i] = C[i][j].y;
    }
    for (int o = 0; o < 5; o++) {
        float s = 0.f;
        for (int q = 0; q < NQ; q++) {
            float zs = ((j >> (NQ - 1 - q)) & 1) ? -1.f : 1.f;
            s += zs * Wc[o * NQ + q];
        }
        g_Mz[o * DIM + j] = s;
    }
    // LayerNorm-fold constants
    for (int q = 0; q < NQ; q++)
        g_W2g[q * DIM + j] = W2[q * DIM + j] * lng[j];
    if (j < NQ) {
        float sg = 0.f, cq = b2[j];
        for (int i = 0; i < DIM; i++) {
            sg += W2[j * DIM + i] * lng[i];
            cq += lnb[i] * W2[j * DIM + i];
        }
        g_Sg[j] = sg;
        g_Cq[j] = cq;
    }
}

// smem layout (floats)
#define OFF_W1T  0
#define OFF_CRT  (OFF_W1T + DIM * PW)          // 4608
#define OFF_CIT  (OFF_CRT + DIM * PW)          // 9216
#define OFF_W2G  (OFF_CIT + DIM * PW)          // 13824
#define OFF_MZT  (OFF_W2G + NQ * PW)           // 14256
#define OFF_B1   (OFF_MZT + 5 * PW)            // 14616
#define OFF_BC   (OFF_B1 + DIM)                // 14680
#define OFF_SG   (OFF_BC + 8)                  // 14688
#define OFF_CQ   (OFF_SG + 8)                  // 14696
#define OFF_AT   (OFF_CQ + 8)                  // 14704 (mult of 4 -> 16B aligned)
#define SMEM_FLOATS (OFF_AT + DIM * PA)        // 41328 -> ~165.3 KB

// transpose-reduce: sum v[s] over 8 tx lanes; lane tx returns value for s == tx
__device__ __forceinline__ float txreduce8(float* v, int tx) {
    #pragma unroll
    for (int a = 0; a < 8; a++) v[a] += __shfl_xor_sync(0xffffffffu, v[a], 4);
    float v4[4];
    #pragma unroll
    for (int a = 0; a < 4; a++) v4[a] = (tx & 4) ? v[4 + a] : v[a];
    #pragma unroll
    for (int a = 0; a < 4; a++) v4[a] += __shfl_xor_sync(0xffffffffu, v4[a], 2);
    float v2[2];
    #pragma unroll
    for (int a = 0; a < 2; a++) v2[a] = (tx & 2) ? v4[2 + a] : v4[a];
    #pragma unroll
    for (int a = 0; a < 2; a++) v2[a] += __shfl_xor_sync(0xffffffffu, v2[a], 1);
    return (tx & 1) ? v2[1] : v2[0];
}

__global__ __launch_bounds__(NTHR, 1)
void qmaml_main_kernel(const float* __restrict__ x,
                       const float* __restrict__ W1,
                       const float* __restrict__ b1,
                       const float* __restrict__ bc,
                       float* __restrict__ out,
                       int nIter, int B) {
    extern __shared__ float sm[];
    float* sW1T = sm + OFF_W1T;   // [j][ish(i)]
    float* sCRT = sm + OFF_CRT;
    float* sCIT = sm + OFF_CIT;
    float* sW2g = sm + OFF_W2G;   // [q][ish(i)]
    float* sMzT = sm + OFF_MZT;   // [o][ish(i)]
    float* sB1  = sm + OFF_B1;
    float* sBc  = sm + OFF_BC;
    float* sSg  = sm + OFF_SG;
    float* sCq  = sm + OFF_CQ;
    float* sAT  = sm + OFF_AT;    // unified X/psi tile, [j][raw col], pitch 416
                                  // BOTH phases use col = sample + 2*(j>>2):
                                  // per-row per-warp sets identical across phases -> no cross-warp aliasing

    const int tid = threadIdx.x;

    // ---- load shared weights once (whole CTA) ----
    for (int idx = tid; idx < DIM * DIM; idx += NTHR) {
        int j = idx >> 6, i = idx & 63;
        int d = j * PW + ish(i);
        sW1T[d] = W1[i * DIM + j];    // W1 [i][j] row-major -> [j][i]
        sCRT[d] = g_CRT[idx];         // already [j][i]
        sCIT[d] = g_CIT[idx];
    }
    for (int idx = tid; idx < 5 * DIM; idx += NTHR) {
        int o = idx >> 6, i = idx & 63;
        sMzT[o * PW + ish(i)] = g_Mz[idx];
    }
    for (int idx = tid; idx < NQ * DIM; idx += NTHR) {
        int q = idx >> 6, i = idx & 63;
        sW2g[q * PW + ish(i)] = g_W2g[idx];
    }
    if (tid < DIM) sB1[tid] = b1[tid];
    if (tid < NQ) { sSg[tid] = g_Sg[tid]; sCq[tid] = g_Cq[tid]; }
    if (tid < 5) sBc[tid] = bc[tid];
    __syncthreads();

    const int w   = tid >> 5;           // warp 0..11 -> samples 32w..32w+31
    const int l   = tid & 31;           // lane
    const int tx  = l & 7;              // i-lane within octet
    const int oct = l >> 3;             // octet 0..3
    const int s0g = 32 * w + 8 * oct;   // first sample of this thread's 8
    const int i0  = tx * 8;
    const int ish0 = ish(i0);

    for (int iter = blockIdx.x; iter < nIter; iter += gridDim.x) {
        int sbase = iter * SPT + 32 * w;
        if (sbase >= B) continue;       // warp-uniform tail guard (tail is whole warps)

        const float4* xg4 = (const float4*)(x + (size_t)sbase * DIM);

        __syncwarp();   // all lanes past previous iter's reads of sAT

        // ---- stage this warp's 32 samples into sAT (coalesced LDG, CF STS) ----
        // col = 32w + sl + 2*(j>>2)  (raw, max 413 < PA)
        #pragma unroll
        for (int m = 0; m < 16; m++) {
            int idx = m * 32 + l;                // 512 float4 per warp
            float4 v = xg4[idx];
            int sl = idx >> 4;                   // local sample 0..31
            int j0 = (idx & 15) << 2;            // row group
            int col = 32 * w + sl + (j0 >> 1);   // rot = 2*(j0>>2) = j0>>1
            float* p = sAT + col;
            p[(j0 + 0) * PA] = v.x;
            p[(j0 + 1) * PA] = v.y;
            p[(j0 + 2) * PA] = v.z;
            p[(j0 + 3) * PA] = v.w;
        }
        __syncwarp();

        // ---- GEMM1: acc[s][ipair] over j ----
        ull acc[8][4];
        #pragma unroll
        for (int s = 0; s < 8; s++)
            #pragma unroll
            for (int q = 0; q < 4; q++) acc[s][q] = 0ull;

        #pragma unroll 4
        for (int j = 0; j < DIM; j++) {
            const float* ap = sAT + j * PA + (s0g + 2 * (j >> 2));
            float2 a01 = *(const float2*)(ap);
            float2 a23 = *(const float2*)(ap + 2);
            float2 a45 = *(const float2*)(ap + 4);
            float2 a67 = *(const float2*)(ap + 6);
            const float* bp = sW1T + j * PW + ish0;
            ulonglong2 b01 = *(const ulonglong2*)bp;
            ulonglong2 b23 = *(const ulonglong2*)(bp + 4);
            ull ad[8];
            ad[0] = dup2(a01.x); ad[1] = dup2(a01.y);
            ad[2] = dup2(a23.x); ad[3] = dup2(a23.y);
            ad[4] = dup2(a45.x); ad[5] = dup2(a45.y);
            ad[6] = dup2(a67.x); ad[7] = dup2(a67.y);
            #pragma unroll
            for (int s = 0; s < 8; s++) {
                ffma2(acc[s][0], ad[s], b01.x);
                ffma2(acc[s][1], ad[s], b01.y);
                ffma2(acc[s][2], ad[s], b23.x);
                ffma2(acc[s][3], ad[s], b23.y);
            }
        }

        // ---- bias + relu; LN stats + z-dots on RAW h (LN folded into z) ----
        float h[8][8];
        {
            float bb[8];
            #pragma unroll
            for (int c = 0; c < 8; c++) bb[c] = sB1[i0 + c];
            #pragma unroll
            for (int s = 0; s < 8; s++)
                #pragma unroll
                for (int q = 0; q < 4; q++) {
                    float2 f = *(float2*)&acc[s][q];
                    h[s][2 * q]     = fmaxf(f.x + bb[2 * q], 0.f);
                    h[s][2 * q + 1] = fmaxf(f.y + bb[2 * q + 1], 0.f);
                }
        }
        float vec[12];
        {
            float su[8], sq[8], zp[8][NQ];
            #pragma unroll
            for (int s = 0; s < 8; s++) {
                float a = 0.f, b = 0.f;
                #pragma unroll
                for (int c = 0; c < 8; c++) { a += h[s][c]; b += h[s][c] * h[s][c]; }
                su[s] = a; sq[s] = b;
            }
            #pragma unroll
            for (int q = 0; q < NQ; q++) {
                const float* wp = sW2g + q * PW + ish0;
                float4 wa = *(const float4*)wp;
                float4 wb = *(const float4*)(wp + 4);
                float ww[8] = { wa.x, wa.y, wa.z, wa.w, wb.x, wb.y, wb.z, wb.w };
                #pragma unroll
                for (int s = 0; s < 8; s++) {
                    float d = 0.f;
                    #pragma unroll
                    for (int c = 0; c < 8; c++) d += h[s][c] * ww[c];
                    zp[s][q] = d;
                }
            }
            // reduce 8 quantities across tx lanes; lane tx owns sample s0g+tx = 32w+l
            float S = txreduce8(su, tx);
            float Q = txreduce8(sq, tx);
            float D[NQ];
            #pragma unroll
            for (int q = 0; q < NQ; q++) {
                float v[8];
                #pragma unroll
                for (int s = 0; s < 8; s++) v[s] = zp[s][q];
                D[q] = txreduce8(v, tx);
            }
            float mu  = S * (1.f / DIM);
            float var = Q * (1.f / DIM) - mu * mu;
            float inv = rsqrtf(var + 1e-5f);
            #pragma unroll
            for (int q = 0; q < NQ; q++) {
                float z  = fast_tanh(inv * (D[q] - mu * sSg[q]) + sCq[q]);
                float hh = 1.5707963267948966f * z;
                float sn, cs;
                __sincosf(hh, &sn, &cs);
                vec[2 * q]     = cs;
                vec[2 * q + 1] = sn;
            }
        }

        __syncwarp();   // all lanes done reading X from sAT before psi overwrites

        // ---- psi0: lane = its own sample (32w + l); build 64 amplitudes ----
        // SAME column map as X: col = sg + 2*(j>>2) -> overwrites only this warp's X cells
        {
            int sg = 32 * w + l;
            float t2[2], t4[4], t8[8], t16[16], t32[32], p6[64];
            t2[0] = vec[0]; t2[1] = vec[1];
            #pragma unroll
            for (int k = 0; k < 2; k++) { t4[2*k] = t2[k]*vec[2]; t4[2*k+1] = t2[k]*vec[3]; }
            #pragma unroll
            for (int k = 0; k < 4; k++) { t8[2*k] = t4[k]*vec[4]; t8[2*k+1] = t4[k]*vec[5]; }
            #pragma unroll
            for (int k = 0; k < 8; k++) { t16[2*k] = t8[k]*vec[6]; t16[2*k+1] = t8[k]*vec[7]; }
            #pragma unroll
            for (int k = 0; k < 16; k++) { t32[2*k] = t16[k]*vec[8]; t32[2*k+1] = t16[k]*vec[9]; }
            #pragma unroll
            for (int k = 0; k < 32; k++) { p6[2*k] = t32[k]*vec[10]; p6[2*k+1] = t32[k]*vec[11]; }
            #pragma unroll
            for (int j = 0; j < DIM; j++) {
                int col = sg + 2 * (j >> 2);
                sAT[j * PA + col] = p6[j];
            }
        }
        __syncwarp();

        // ---- GEMM2/3 split over i-halves (4 cols each) to cap registers ----
        float vals[8][5];
        #pragma unroll
        for (int s = 0; s < 8; s++)
            #pragma unroll
            for (int o = 0; o < 5; o++) vals[s][o] = 0.f;

        #pragma unroll
        for (int hf = 0; hf < 2; hf++) {
            const int ishh = ish(i0 + 4 * hf);   // 4-col block never crosses the 32-boundary
            ull aR[8][2], aI[8][2];
            #pragma unroll
            for (int s = 0; s < 8; s++) {
                aR[s][0] = 0ull; aR[s][1] = 0ull;
                aI[s][0] = 0ull; aI[s][1] = 0ull;
            }
            #pragma unroll 4
            for (int j = 0; j < DIM; j++) {
                const float* ap = sAT + j * PA + (s0g + 2 * (j >> 2));
                float2 a01 = *(const float2*)(ap);
                float2 a23 = *(const float2*)(ap + 2);
                float2 a45 = *(const float2*)(ap + 4);
                float2 a67 = *(const float2*)(ap + 6);
                ulonglong2 rr = *(const ulonglong2*)(sCRT + j * PW + ishh);
                ulonglong2 ii = *(const ulonglong2*)(sCIT + j * PW + ishh);
                ull ad[8];
                ad[0] = dup2(a01.x); ad[1] = dup2(a01.y);
                ad[2] = dup2(a23.x); ad[3] = dup2(a23.y);
                ad[4] = dup2(a45.x); ad[5] = dup2(a45.y);
                ad[6] = dup2(a67.x); ad[7] = dup2(a67.y);
                #pragma unroll
                for (int s = 0; s < 8; s++) {
                    ffma2(aR[s][0], ad[s], rr.x);
                    ffma2(aR[s][1], ad[s], rr.y);
                    ffma2(aI[s][0], ad[s], ii.x);
                    ffma2(aI[s][1], ad[s], ii.y);
                }
            }
            // probs for this i-half -> Mz partial accumulation
            ulonglong2 mz[5];
            #pragma unroll
            for (int o = 0; o < 5; o++)
                mz[o] = *(const ulonglong2*)(sMzT + o * PW + ishh);
            #pragma unroll
            for (int s = 0; s < 8; s++) {
                ull pp0 = 0ull, pp1 = 0ull;
                ffma2(pp0, aR[s][0], aR[s][0]);
                ffma2(pp0, aI[s][0], aI[s][0]);
                ffma2(pp1, aR[s][1], aR[s][1]);
                ffma2(pp1, aI[s][1], aI[s][1]);
                #pragma unroll
                for (int o = 0; o < 5; o++) {
                    ull a5 = 0ull;
                    ffma2(a5, pp0, mz[o].x);
                    ffma2(a5, pp1, mz[o].y);
                    float2 f = *(float2*)&a5;
                    vals[s][o] += f.x + f.y;
                }
            }
        }

        // ---- transpose-reduce -> gmem ----
        {
            size_t og = ((size_t)iter * SPT + 32 * w + l) * 5;
            #pragma unroll
            for (int o = 0; o < 5; o++) {
                float v[8];
                #pragma unroll
                for (int s = 0; s < 8; s++) v[s] = vals[s][o];
                float r = txreduce8(v, tx);     // lane l gets sample 32w+l
                out[og + o] = r + sBc[o];
            }
        }
    }
}

extern "C" void kernel_launch(void* const* d_in, const int* in_sizes, int n_in,
                              void* d_out, int out_size) {
    const float* x     = (const float*)d_in[0];
    const float* W1    = (const float*)d_in[1];
    const float* b1    = (const float*)d_in[2];
    const float* ln_g  = (const float*)d_in[3];
    const float* ln_b  = (const float*)d_in[4];
    const float* W2    = (const float*)d_in[5];
    const float* b2    = (const float*)d_in[6];
    const float* th_sh = (const float*)d_in[7];
    const float* th_tk = (const float*)d_in[8];
    const float* Wc    = (const float*)d_in[9];
    const float* bc    = (const float*)d_in[10];
    float* out = (float*)d_out;

    int B = in_sizes[0] / DIM;
    int nIter = (B + SPT - 1) / SPT;

    setup_kernel<<<1, 64>>>(th_sh, th_tk, Wc, W2, ln_g, ln_b, b2);

    size_t smem = (size_t)SMEM_FLOATS * sizeof(float);
    cudaFuncSetAttribute(qmaml_main_kernel,
                         cudaFuncAttributeMaxDynamicSharedMemorySize, (int)smem);

    int grid = 152;
    if (grid > nIter) grid = nIter;
    qmaml_main_kernel<<<grid, NTHR, smem>>>(x, W1, b1, bc, out, nIter, B);
}

// round 14
// speedup vs baseline: 1.9159x; 1.9159x over previous
#include <cuda_runtime.h>
#include <math.h>

#define NQ   6
#define DIM  64
#define SPT  256        // samples per iteration per CTA (32 per warp)
#define PW   72         // weight pitch (words), half-shift layout
#define PAX  264        // X tile pitch: 256 cols + 8 mirror
#define PAP  256        // psi tile pitch (no pad needed: offsets stay multiples of 8)

typedef unsigned long long ull;

__device__ float g_CRT[DIM * DIM];   // [j][i]
__device__ float g_CIT[DIM * DIM];   // [j][i]
__device__ float g_Mz[5 * DIM];      // [o][i]
__device__ float g_W2g[NQ * DIM];    // W2[q][i] * ln_g[i]
__device__ float g_Sg[NQ];           // sum_i W2[q][i]*g[i]
__device__ float g_Cq[NQ];           // sum_i lnb[i]*W2[q][i] + b2[q]

__device__ __forceinline__ void ffma2(ull &d, ull a, ull b) {
    asm("fma.rn.f32x2 %0, %1, %2, %0;" : "+l"(d) : "l"(a), "l"(b));
}
__device__ __forceinline__ ull dup2(float v) {
    ull r; asm("mov.b64 %0, {%1, %1};" : "=l"(r) : "f"(v)); return r;
}
// half-shift: words i>=32 shifted +4 so 8 lanes at 32B stride hit distinct bank quads
__device__ __forceinline__ int ish(int i) { return i + ((i >> 5) << 2); }

__device__ __forceinline__ float fast_tanh(float x) {
    float e = __expf(-2.f * fabsf(x));
    float t = __fdividef(1.f - e, 1.f + e);
    return copysignf(t, x);
}

__device__ __forceinline__ int ring_map(int r, int i) {
    int v = i;
    for (int w = NQ - 1; w >= 0; --w) {
        int t = (w + r) % NQ;
        v ^= ((v >> (NQ - 1 - w)) & 1) << (NQ - 1 - t);
    }
    return v;
}

// Parallel setup: 1024 threads = 64 columns x 16 pair-threads.
// Each sweep applies one qubit rotation to all 32 row-pairs of all 64 columns.
__global__ __launch_bounds__(1024, 1)
void setup_kernel(const float* __restrict__ th_sh,
                  const float* __restrict__ th_tk,
                  const float* __restrict__ Wc,
                  const float* __restrict__ W2,
                  const float* __restrict__ lng,
                  const float* __restrict__ lnb,
                  const float* __restrict__ b2) {
    __shared__ float2 C[DIM][DIM];   // C[i][j]
    const int tid = threadIdx.x;
    const int j   = tid & 63;        // column
    const int pt  = tid >> 6;        // pair-thread 0..15 (2 pairs each)

    // init identity: thread (pt,j) owns rows 4pt..4pt+3 of column j
    #pragma unroll
    for (int r = 0; r < 4; r++) {
        int i = 4 * pt + r;
        C[i][j] = make_float2(i == j ? 1.f : 0.f, 0.f);
    }
    __syncthreads();

    const float* TH[3] = { th_sh, th_sh + NQ * 3, th_tk };
    const int    RS[3] = { 1, 2, 1 };

    for (int l = 0; l < 3; l++) {
        const float* th = TH[l];
        for (int w = 0; w < NQ; w++) {
            float phi = th[w * 3 + 0], te = th[w * 3 + 1], om = th[w * 3 + 2];
            float sth, cth; sincosf(0.5f * te, &sth, &cth);
            float a = 0.5f * (phi + om), b = 0.5f * (phi - om);
            float sa, ca, sb, cb;
            sincosf(a, &sa, &ca);
            sincosf(b, &sb, &cb);
            float2 R00 = make_float2( ca * cth, -sa * cth);   // em*c
            float2 R01 = make_float2(-cb * sth, -sb * sth);   // -ep*s
            float2 R10 = make_float2( cb * sth, -sb * sth);   // conj(ep)*s
            float2 R11 = make_float2( ca * cth,  sa * cth);   // conj(em)*c
            int bit = 1 << (NQ - 1 - w);
            #pragma unroll
            for (int pp = 0; pp < 2; pp++) {
                int p  = 2 * pt + pp;            // pair index 0..31
                int lo = p & (bit - 1);
                int hi = p - lo;
                int i0 = (hi << 1) | lo;
                int i1 = i0 | bit;
                float2 v0 = C[i0][j], v1 = C[i1][j];
                C[i0][j] = make_float2(
                    R00.x * v0.x - R00.y * v0.y + R01.x * v1.x - R01.y * v1.y,
                    R00.x * v0.y + R00.y * v0.x + R01.x * v1.y + R01.y * v1.x);
                C[i1][j] = make_float2(
                    R10.x * v0.x - R10.y * v0.y + R11.x * v1.x - R11.y * v1.y,
                    R10.x * v0.y + R10.y * v0.x + R11.x * v1.y + R11.y * v1.x);
            }
            __syncthreads();
        }
        // row permutation: newC[i][:] = C[ring[i]][:]  (stash in regs, barrier, write)
        float2 tmp[4];
        #pragma unroll
        for (int r = 0; r < 4; r++)
            tmp[r] = C[ring_map(RS[l], 4 * pt + r)][j];
        __syncthreads();
        #pragma unroll
        for (int r = 0; r < 4; r++)
            C[4 * pt + r][j] = tmp[r];
        __syncthreads();
    }

    // write out C transposed: g_CRT[j][i] = C[i][j]
    #pragma unroll
    for (int r = 0; r < 4; r++) {
        int i = 4 * pt + r;
        g_CRT[j * DIM + i] = C[i][j].x;
        g_CIT[j * DIM + i] = C[i][j].y;
    }

    if (pt == 0) {   // tid == j, 64 threads
        for (int o = 0; o < 5; o++) {
            float s = 0.f;
            for (int q = 0; q < NQ; q++) {
                float zs = ((j >> (NQ - 1 - q)) & 1) ? -1.f : 1.f;
                s += zs * Wc[o * NQ + q];
            }
            g_Mz[o * DIM + j] = s;
        }
        for (int q = 0; q < NQ; q++)
            g_W2g[q * DIM + j] = W2[q * DIM + j] * lng[j];
        if (j < NQ) {
            float sg = 0.f, cq = b2[j];
            for (int i = 0; i < DIM; i++) {
                sg += W2[j * DIM + i] * lng[i];
                cq += lnb[i] * W2[j * DIM + i];
            }
            g_Sg[j] = sg;
            g_Cq[j] = cq;
        }
    }
}

// smem layout (floats)
#define OFF_W1T  0
#define OFF_CRT  (OFF_W1T + DIM * PW)          // 4608
#define OFF_CIT  (OFF_CRT + DIM * PW)          // 9216
#define OFF_W2G  (OFF_CIT + DIM * PW)          // 13824
#define OFF_MZT  (OFF_W2G + NQ * PW)           // 14256
#define OFF_B1   (OFF_MZT + 5 * PW)            // 14616
#define OFF_BC   (OFF_B1 + DIM)                // 14680
#define OFF_SG   (OFF_BC + 8)                  // 14688
#define OFF_CQ   (OFF_SG + 8)                  // 14696
#define OFF_ATX  (OFF_CQ + 8)                  // 14704 (mult of 4 -> 16B aligned)
#define OFF_ATP  (OFF_ATX + DIM * PAX)         // 31600
#define SMEM_FLOATS (OFF_ATP + DIM * PAP)      // 47984 -> ~192 KB

// transpose-reduce: sum v[s] over 8 tx lanes; lane tx returns value for s == tx
__device__ __forceinline__ float txreduce8(float* v, int tx) {
    #pragma unroll
    for (int a = 0; a < 8; a++) v[a] += __shfl_xor_sync(0xffffffffu, v[a], 4);
    float v4[4];
    #pragma unroll
    for (int a = 0; a < 4; a++) v4[a] = (tx & 4) ? v[4 + a] : v[a];
    #pragma unroll
    for (int a = 0; a < 4; a++) v4[a] += __shfl_xor_sync(0xffffffffu, v4[a], 2);
    float v2[2];
    #pragma unroll
    for (int a = 0; a < 2; a++) v2[a] = (tx & 2) ? v4[2 + a] : v4[a];
    #pragma unroll
    for (int a = 0; a < 2; a++) v2[a] += __shfl_xor_sync(0xffffffffu, v2[a], 1);
    return (tx & 1) ? v2[1] : v2[0];
}

__global__ __launch_bounds__(256, 1)
void qmaml_main_kernel(const float* __restrict__ x,
                       const float* __restrict__ W1,
                       const float* __restrict__ b1,
                       const float* __restrict__ bc,
                       float* __restrict__ out,
                       int nIter) {
    extern __shared__ float sm[];
    float* sW1T = sm + OFF_W1T;   // [j][ish(i)]
    float* sCRT = sm + OFF_CRT;
    float* sCIT = sm + OFF_CIT;
    float* sW2g = sm + OFF_W2G;   // [q][ish(i)]
    float* sMzT = sm + OFF_MZT;   // [o][ish(i)]
    float* sB1  = sm + OFF_B1;
    float* sBc  = sm + OFF_BC;
    float* sSg  = sm + OFF_SG;
    float* sCq  = sm + OFF_CQ;
    float* sATX = sm + OFF_ATX;   // [j][(s + 2*(j>>2)) & 255], pitch 264, 8 mirror cols
    float* sATP = sm + OFF_ATP;   // [j][(s + 8*((j>>2)&3)) & 255], pitch 256

    const int tid = threadIdx.x;

    // ---- load shared weights once (whole CTA) ----
    for (int idx = tid; idx < DIM * DIM; idx += 256) {
        int j = idx >> 6, i = idx & 63;
        int d = j * PW + ish(i);
        sW1T[d] = W1[i * DIM + j];    // W1 [i][j] row-major -> [j][i]
        sCRT[d] = g_CRT[idx];         // already [j][i]
        sCIT[d] = g_CIT[idx];
    }
    for (int idx = tid; idx < 5 * DIM; idx += 256) {
        int o = idx >> 6, i = idx & 63;
        sMzT[o * PW + ish(i)] = g_Mz[idx];
    }
    for (int idx = tid; idx < NQ * DIM; idx += 256) {
        int q = idx >> 6, i = idx & 63;
        sW2g[q * PW + ish(i)] = g_W2g[idx];
    }
    if (tid < DIM) sB1[tid] = b1[tid];
    if (tid < NQ) { sSg[tid] = g_Sg[tid]; sCq[tid] = g_Cq[tid]; }
    if (tid < 5) sBc[tid] = bc[tid];
    __syncthreads();

    const int w   = tid >> 5;           // warp 0..7  -> samples 32w..32w+31
    const int l   = tid & 31;           // lane
    const int tx  = l & 7;              // i-lane within octet
    const int oct = l >> 3;             // octet 0..3
    const int s0g = 32 * w + 8 * oct;   // first sample of this thread's 8
    const int i0  = tx * 8;
    const int ish0 = ish(i0);

    for (int iter = blockIdx.x; iter < nIter; iter += gridDim.x) {
        const float4* xg4 = (const float4*)(x + ((size_t)iter * SPT + 32 * w) * DIM);

        __syncwarp();   // all lanes past previous iter's reads of sATX/sATP

        // ---- stage this warp's 32 samples into sATX (coalesced LDG, CF STS) ----
        #pragma unroll
        for (int m = 0; m < 16; m++) {
            int idx = m * 32 + l;                // 512 float4 per warp
            float4 v = xg4[idx];
            int sl = idx >> 4;                   // local sample 0..31
            int j0 = (idx & 15) << 2;            // row group
            int col = (32 * w + sl + (j0 >> 1)) & 255;   // rot_X = 2*(j0>>2) = j0>>1
            float* p = sATX + col;
            p[(j0 + 0) * PAX] = v.x;
            p[(j0 + 1) * PAX] = v.y;
            p[(j0 + 2) * PAX] = v.z;
            p[(j0 + 3) * PAX] = v.w;
            if (col < 8) {
                float* pm = p + 256;
                pm[(j0 + 0) * PAX] = v.x;
                pm[(j0 + 1) * PAX] = v.y;
                pm[(j0 + 2) * PAX] = v.z;
                pm[(j0 + 3) * PAX] = v.w;
            }
        }
        __syncwarp();

        // ---- GEMM1: acc[s][ipair] over j ----
        ull acc[8][4];
        #pragma unroll
        for (int s = 0; s < 8; s++)
            #pragma unroll
            for (int q = 0; q < 4; q++) acc[s][q] = 0ull;

        #pragma unroll 4
        for (int j = 0; j < DIM; j++) {
            int c = (s0g + 2 * (j >> 2)) & 255;
            const float* ap = sATX + j * PAX + c;
            float2 a01 = *(const float2*)(ap);
            float2 a23 = *(const float2*)(ap + 2);
            float2 a45 = *(const float2*)(ap + 4);
            float2 a67 = *(const float2*)(ap + 6);
            const float* bp = sW1T + j * PW + ish0;
            ulonglong2 b01 = *(const ulonglong2*)bp;
            ulonglong2 b23 = *(const ulonglong2*)(bp + 4);
            ull ad[8];
            ad[0] = dup2(a01.x); ad[1] = dup2(a01.y);
            ad[2] = dup2(a23.x); ad[3] = dup2(a23.y);
            ad[4] = dup2(a45.x); ad[5] = dup2(a45.y);
            ad[6] = dup2(a67.x); ad[7] = dup2(a67.y);
            #pragma unroll
            for (int s = 0; s < 8; s++) {
                ffma2(acc[s][0], ad[s], b01.x);
                ffma2(acc[s][1], ad[s], b01.y);
                ffma2(acc[s][2], ad[s], b23.x);
                ffma2(acc[s][3], ad[s], b23.y);
            }
        }

        // ---- bias + relu; LN stats + z-dots on RAW h (LN folded into z) ----
        float h[8][8];
        {
            float bb[8];
            #pragma unroll
            for (int c = 0; c < 8; c++) bb[c] = sB1[i0 + c];
            #pragma unroll
            for (int s = 0; s < 8; s++)
                #pragma unroll
                for (int q = 0; q < 4; q++) {
                    float2 f = *(float2*)&acc[s][q];
                    h[s][2 * q]     = fmaxf(f.x + bb[2 * q], 0.f);
                    h[s][2 * q + 1] = fmaxf(f.y + bb[2 * q + 1], 0.f);
                }
        }
        float vec[12];
        {
            float su[8], sq[8], zp[8][NQ];
            #pragma unroll
            for (int s = 0; s < 8; s++) {
                float a = 0.f, b = 0.f;
                #pragma unroll
                for (int c = 0; c < 8; c++) { a += h[s][c]; b += h[s][c] * h[s][c]; }
                su[s] = a; sq[s] = b;
            }
            #pragma unroll
            for (int q = 0; q < NQ; q++) {
                const float* wp = sW2g + q * PW + ish0;
                float4 wa = *(const float4*)wp;
                float4 wb = *(const float4*)(wp + 4);
                float ww[8] = { wa.x, wa.y, wa.z, wa.w, wb.x, wb.y, wb.z, wb.w };
                #pragma unroll
                for (int s = 0; s < 8; s++) {
                    float d = 0.f;
                    #pragma unroll
                    for (int c = 0; c < 8; c++) d += h[s][c] * ww[c];
                    zp[s][q] = d;
                }
            }
            // reduce 8 quantities across tx lanes; lane tx owns sample s0g+tx = 32w+l
            float S = txreduce8(su, tx);
            float Q = txreduce8(sq, tx);
            float D[NQ];
            #pragma unroll
            for (int q = 0; q < NQ; q++) {
                float v[8];
                #pragma unroll
                for (int s = 0; s < 8; s++) v[s] = zp[s][q];
                D[q] = txreduce8(v, tx);
            }
            float mu  = S * (1.f / DIM);
            float var = Q * (1.f / DIM) - mu * mu;
            float inv = rsqrtf(var + 1e-5f);
            #pragma unroll
            for (int q = 0; q < NQ; q++) {
                float z  = fast_tanh(inv * (D[q] - mu * sSg[q]) + sCq[q]);
                float hh = 1.5707963267948966f * z;
                float sn, cs;
                __sincosf(hh, &sn, &cs);
                vec[2 * q]     = cs;
                vec[2 * q + 1] = sn;
            }
        }

        // ---- psi0: lane = its own sample (32w + l); build 64 amplitudes ----
        {
            int sg = 32 * w + l;
            float t2[2], t4[4], t8[8], t16[16], t32[32], p6[64];
            t2[0] = vec[0]; t2[1] = vec[1];
            #pragma unroll
            for (int k = 0; k < 2; k++) { t4[2*k] = t2[k]*vec[2]; t4[2*k+1] = t2[k]*vec[3]; }
            #pragma unroll
            for (int k = 0; k < 4; k++) { t8[2*k] = t4[k]*vec[4]; t8[2*k+1] = t4[k]*vec[5]; }
            #pragma unroll
            for (int k = 0; k < 8; k++) { t16[2*k] = t8[k]*vec[6]; t16[2*k+1] = t8[k]*vec[7]; }
            #pragma unroll
            for (int k = 0; k < 16; k++) { t32[2*k] = t16[k]*vec[8]; t32[2*k+1] = t16[k]*vec[9]; }
            #pragma unroll
            for (int k = 0; k < 32; k++) { p6[2*k] = t32[k]*vec[10]; p6[2*k+1] = t32[k]*vec[11]; }
            #pragma unroll
            for (int j = 0; j < DIM; j++) {
                int col = (sg + ((j >> 2) & 3) * 8) & 255;
                sATP[j * PAP + col] = p6[j];
            }
        }
        __syncwarp();

        // ---- GEMM2/3: psiR/psiI = psi0 @ C^T ----
        ull aR[8][4], aI[8][4];
        #pragma unroll
        for (int s = 0; s < 8; s++)
            #pragma unroll
            for (int q = 0; q < 4; q++) { aR[s][q] = 0ull; aI[s][q] = 0ull; }

        #pragma unroll 4
        for (int j = 0; j < DIM; j++) {
            int c = (s0g + ((j >> 2) & 3) * 8) & 255;
            const float* ap = sATP + j * PAP + c;
            float4 al = *(const float4*)ap;
            float4 ah = *(const float4*)(ap + 4);
            const float* rp = sCRT + j * PW + ish0;
            const float* ip = sCIT + j * PW + ish0;
            ulonglong2 r01 = *(const ulonglong2*)rp;
            ulonglong2 r23 = *(const ulonglong2*)(rp + 4);
            ulonglong2 i01 = *(const ulonglong2*)ip;
            ulonglong2 i23 = *(const ulonglong2*)(ip + 4);
            ull ad[8];
            ad[0] = dup2(al.x); ad[1] = dup2(al.y); ad[2] = dup2(al.z); ad[3] = dup2(al.w);
            ad[4] = dup2(ah.x); ad[5] = dup2(ah.y); ad[6] = dup2(ah.z); ad[7] = dup2(ah.w);
            #pragma unroll
            for (int s = 0; s < 8; s++) {
                ffma2(aR[s][0], ad[s], r01.x);
                ffma2(aR[s][1], ad[s], r01.y);
                ffma2(aR[s][2], ad[s], r23.x);
                ffma2(aR[s][3], ad[s], r23.y);
                ffma2(aI[s][0], ad[s], i01.x);
                ffma2(aI[s][1], ad[s], i01.y);
                ffma2(aI[s][2], ad[s], i23.x);
                ffma2(aI[s][3], ad[s], i23.y);
            }
        }

        // ---- probs -> Mz partials -> transpose-reduce -> gmem ----
        {
            ulonglong2 mza[5], mzb[5];
            #pragma unroll
            for (int o = 0; o < 5; o++) {
                const float* mp = sMzT + o * PW + ish0;
                mza[o] = *(const ulonglong2*)mp;
                mzb[o] = *(const ulonglong2*)(mp + 4);
            }
            float vals[8][5];
            #pragma unroll
            for (int s = 0; s < 8; s++) {
                ull pp[4];
                #pragma unroll
                for (int q = 0; q < 4; q++) {
                    pp[q] = 0ull;
                    ffma2(pp[q], aR[s][q], aR[s][q]);
                    ffma2(pp[q], aI[s][q], aI[s][q]);
                }
                #pragma unroll
                for (int o = 0; o < 5; o++) {
                    ull a5 = 0ull;
                    ffma2(a5, pp[0], mza[o].x);
                    ffma2(a5, pp[1], mza[o].y);
                    ffma2(a5, pp[2], mzb[o].x);
                    ffma2(a5, pp[3], mzb[o].y);
                    float2 f = *(float2*)&a5;
                    vals[s][o] = f.x + f.y;
                }
            }
            size_t og = ((size_t)iter * SPT + 32 * w + l) * 5;
            #pragma unroll
            for (int o = 0; o < 5; o++) {
                float v[8];
                #pragma unroll
                for (int s = 0; s < 8; s++) v[s] = vals[s][o];
                float r = txreduce8(v, tx);     // lane l gets sample 32w+l
                out[og + o] = r + sBc[o];
            }
        }
    }
}

extern "C" void kernel_launch(void* const* d_in, const int* in_sizes, int n_in,
                              void* d_out, int out_size) {
    const float* x     = (const float*)d_in[0];
    const float* W1    = (const float*)d_in[1];
    const float* b1    = (const float*)d_in[2];
    const float* ln_g  = (const float*)d_in[3];
    const float* ln_b  = (const float*)d_in[4];
    const float* W2    = (const float*)d_in[5];
    const float* b2    = (const float*)d_in[6];
    const float* th_sh = (const float*)d_in[7];
    const float* th_tk = (const float*)d_in[8];
    const float* Wc    = (const float*)d_in[9];
    const float* bc    = (const float*)d_in[10];
    float* out = (float*)d_out;

    int B = in_sizes[0] / DIM;
    int nIter = B / SPT;

    setup_kernel<<<1, 1024>>>(th_sh, th_tk, Wc, W2, ln_g, ln_b, b2);

    size_t smem = (size_t)SMEM_FLOATS * sizeof(float);
    cudaFuncSetAttribute(qmaml_main_kernel,
                         cudaFuncAttributeMaxDynamicSharedMemorySize, (int)smem);

    int grid = 128;                  // 512 tiles / 128 blocks = 4 each, balanced
    if (grid > nIter) grid = nIter;
    qmaml_main_kernel<<<grid, 256, smem>>>(x, W1, b1, bc, out, nIter);
}

// round 17
// speedup vs baseline: 3.0885x; 1.6120x over previous
#include <cuda_runtime.h>
#include <cuda_bf16.h>
#include <math.h>
#include <cstdint>

#define NQ  6
#define DIM 64

typedef unsigned long long ull;

// ---- pre-swizzled bf16 weight images (exact smem byte layout) ----
__device__ __align__(16) __nv_bfloat16 g_W1hi[DIM * DIM];
__device__ __align__(16) __nv_bfloat16 g_W1lo[DIM * DIM];
__device__ __align__(16) __nv_bfloat16 g_CBhi[2 * DIM * DIM];
__device__ __align__(16) __nv_bfloat16 g_CBlo[2 * DIM * DIM];
__device__ __align__(16) float g_Mz8[DIM * 8];    // [n][o], padded to 8
__device__ __align__(16) float g_W2g8[DIM * 8];   // [c][q], padded to 8
__device__ __align__(16) float g_Sg[8];
__device__ __align__(16) float g_Cq[8];

#define SW128(b) ((b) ^ (((b) >> 3) & 0x70))

__device__ __forceinline__ uint32_t smem_to_u32(const void* p) {
    uint32_t a;
    asm("{ .reg .u64 t; cvta.to.shared.u64 t, %1; cvt.u32.u64 %0, t; }" : "=r"(a) : "l"(p));
    return a;
}
__device__ __forceinline__ float fast_tanh(float x) {
    float e = __expf(-2.f * fabsf(x));
    float t = __fdividef(1.f - e, 1.f + e);
    return copysignf(t, x);
}
__device__ __forceinline__ int ring_map(int r, int i) {
    int v = i;
    for (int w = NQ - 1; w >= 0; --w) {
        int t = (w + r) % NQ;
        v ^= ((v >> (NQ - 1 - w)) & 1) << (NQ - 1 - t);
    }
    return v;
}

// ldmatrix x4, non-transposed, b16
#define LDMX4(r, a) \
    asm volatile("ldmatrix.sync.aligned.m8n8.x4.shared.b16 {%0,%1,%2,%3}, [%4];" \
        : "=r"((r)[0]), "=r"((r)[1]), "=r"((r)[2]), "=r"((r)[3]) : "r"(a))

// mma m16n8k16 row.col f32.bf16.bf16.f32, D += A*B
__device__ __forceinline__ void mma_bf16(float* d, const uint32_t* a,
                                         uint32_t b0, uint32_t b1) {
    asm volatile("mma.sync.aligned.m16n8k16.row.col.f32.bf16.bf16.f32 "
                 "{%0,%1,%2,%3}, {%4,%5,%6,%7}, {%8,%9}, {%0,%1,%2,%3};"
                 : "+f"(d[0]), "+f"(d[1]), "+f"(d[2]), "+f"(d[3])
                 : "r"(a[0]), "r"(a[1]), "r"(a[2]), "r"(a[3]), "r"(b0), "r"(b1));
}

// ===================== setup: C matrix + swizzled bf16 weight images =====================
__global__ __launch_bounds__(1024, 1)
void setup_kernel(const float* __restrict__ th_sh, const float* __restrict__ th_tk,
                  const float* __restrict__ Wc, const float* __restrict__ W2,
                  const float* __restrict__ lng, const float* __restrict__ lnb,
                  const float* __restrict__ b2, const float* __restrict__ W1) {
    __shared__ float2 C[DIM][DIM];
    const int tid = threadIdx.x;
    const int j   = tid & 63;
    const int pt  = tid >> 6;     // 0..15, 2 pairs each

    #pragma unroll
    for (int r = 0; r < 4; r++) {
        int i = 4 * pt + r;
        C[i][j] = make_float2(i == j ? 1.f : 0.f, 0.f);
    }
    __syncthreads();

    const float* TH[3] = { th_sh, th_sh + NQ * 3, th_tk };
    const int    RS[3] = { 1, 2, 1 };
    for (int l = 0; l < 3; l++) {
        const float* th = TH[l];
        for (int w = 0; w < NQ; w++) {
            float phi = th[w*3+0], te = th[w*3+1], om = th[w*3+2];
            float sth, cth; sincosf(0.5f * te, &sth, &cth);
            float a = 0.5f * (phi + om), b = 0.5f * (phi - om);
            float sa, ca, sb, cb;
            sincosf(a, &sa, &ca); sincosf(b, &sb, &cb);
            float2 R00 = make_float2( ca*cth, -sa*cth);
            float2 R01 = make_float2(-cb*sth, -sb*sth);
            float2 R10 = make_float2( cb*sth, -sb*sth);
            float2 R11 = make_float2( ca*cth,  sa*cth);
            int bit = 1 << (NQ - 1 - w);
            #pragma unroll
            for (int pp = 0; pp < 2; pp++) {
                int p  = 2 * pt + pp;
                int lo = p & (bit - 1);
                int hi = p - lo;
                int i0 = (hi << 1) | lo;
                int i1 = i0 | bit;
                float2 v0 = C[i0][j], v1 = C[i1][j];
                C[i0][j] = make_float2(
                    R00.x*v0.x - R00.y*v0.y + R01.x*v1.x - R01.y*v1.y,
                    R00.x*v0.y + R00.y*v0.x + R01.x*v1.y + R01.y*v1.x);
                C[i1][j] = make_float2(
                    R10.x*v0.x - R10.y*v0.y + R11.x*v1.x - R11.y*v1.y,
                    R10.x*v0.y + R10.y*v0.x + R11.x*v1.y + R11.y*v1.x);
            }
            __syncthreads();
        }
        float2 tmp[4];
        #pragma unroll
        for (int r = 0; r < 4; r++) tmp[r] = C[ring_map(RS[l], 4*pt + r)][j];
        __syncthreads();
        #pragma unroll
        for (int r = 0; r < 4; r++) C[4*pt + r][j] = tmp[r];
        __syncthreads();
    }

    // CB image: rows 0..63 = CR[n][j], rows 64..127 = CI[n-64][j]
    for (int e = tid; e < 2 * DIM * DIM; e += 1024) {
        int ii = e >> 6, jj = e & 63;
        float v = (ii < 64) ? C[ii][jj].x : C[ii - 64][jj].y;
        int b = ii * 128 + jj * 2;
        int sw = SW128(b) >> 1;
        __nv_bfloat16 hv = __float2bfloat16(v);
        g_CBhi[sw] = hv;
        g_CBlo[sw] = __float2bfloat16(v - __bfloat162float(hv));
    }
    // W1 image: rows n=i, cols k
    for (int e = tid; e < DIM * DIM; e += 1024) {
        int i = e >> 6, k = e & 63;
        float v = W1[i * DIM + k];
        int b = i * 128 + k * 2;
        int sw = SW128(b) >> 1;
        __nv_bfloat16 hv = __float2bfloat16(v);
        g_W1hi[sw] = hv;
        g_W1lo[sw] = __float2bfloat16(v - __bfloat162float(hv));
    }
    // Mz8 [n][o], W2g8 [c][q]
    for (int e = tid; e < DIM * 8; e += 1024) {
        int i = e >> 3, o = e & 7;
        float s = 0.f;
        if (o < 5) {
            for (int q = 0; q < NQ; q++) {
                float zs = ((i >> (NQ - 1 - q)) & 1) ? -1.f : 1.f;
                s += zs * Wc[o * NQ + q];
            }
        }
        g_Mz8[e] = s;
        g_W2g8[e] = (o < NQ) ? W2[o * DIM + i] * lng[i] : 0.f;
    }
    if (tid < NQ) {
        float sg = 0.f, cq = b2[tid];
        for (int i = 0; i < DIM; i++) {
            sg += W2[tid * DIM + i] * lng[i];
            cq += lnb[i] * W2[tid * DIM + i];
        }
        g_Sg[tid] = sg;
        g_Cq[tid] = cq;
    }
}

// ===================== smem layout (bytes) =====================
#define SM_AHI    0          // 16384  A tile hi (X then psi), 128 rows x 128B, SW128
#define SM_ALO    16384      // 16384
#define SM_W1HI   32768      // 8192
#define SM_W1LO   40960      // 8192
#define SM_CBHI   49152      // 16384
#define SM_CBLO   65536      // 16384
#define SM_MZ     81920      // 2048
#define SM_W2G    83968      // 2048
#define SM_B1     86016      // 256
#define SM_SG     86272      // 32
#define SM_CQ     86304      // 32
#define SM_BC     86336      // 32
#define SMEM_SZ   86400

__global__ __launch_bounds__(128, 2)
void qmaml_mma_kernel(const float* __restrict__ x,
                      const float* __restrict__ b1g,
                      const float* __restrict__ bcg,
                      float* __restrict__ out,
                      int nSlices) {
    extern __shared__ char smem[];
    const uint32_t sb = smem_to_u32(smem);
    const int tid = threadIdx.x;

    // ---- load weight images + constants ----
    {
        const uint4* s1 = (const uint4*)g_W1hi; uint4* d1 = (uint4*)(smem + SM_W1HI);
        const uint4* s2 = (const uint4*)g_W1lo; uint4* d2 = (uint4*)(smem + SM_W1LO);
        for (int i = tid; i < 512; i += 128) { d1[i] = s1[i]; d2[i] = s2[i]; }
        const uint4* s3 = (const uint4*)g_CBhi; uint4* d3 = (uint4*)(smem + SM_CBHI);
        const uint4* s4 = (const uint4*)g_CBlo; uint4* d4 = (uint4*)(smem + SM_CBLO);
        for (int i = tid; i < 1024; i += 128) { d3[i] = s3[i]; d4[i] = s4[i]; }
        const uint4* s5 = (const uint4*)g_Mz8;  uint4* d5 = (uint4*)(smem + SM_MZ);
        const uint4* s6 = (const uint4*)g_W2g8; uint4* d6 = (uint4*)(smem + SM_W2G);
        for (int i = tid; i < 128; i += 128) { d5[i] = s5[i]; d6[i] = s6[i]; }
        if (tid < 64) ((float*)(smem + SM_B1))[tid] = b1g[tid];
        if (tid < 8)  ((float*)(smem + SM_SG))[tid] = g_Sg[tid];
        if (tid < 8)  ((float*)(smem + SM_CQ))[tid] = g_Cq[tid];
        if (tid < 5)  ((float*)(smem + SM_BC))[tid] = bcg[tid];
    }
    __syncthreads();

    const int w  = tid >> 5, l = tid & 31;
    const int lg = l >> 2, lq = l & 3;
    const int rowLoc = 8 * lq + lg;                 // this lane's owned row (0..31)
    const int a_r = (l & 7) + ((l >> 3) & 1) * 8;   // A ldmatrix row-in-16
    const int a_k = (l >> 4) & 1;                   // A ldmatrix k-chunk
    const int b_r = (l & 7) + ((l >> 4) & 1) * 8;   // B ldmatrix row-in-16
    const int b_k = (l >> 3) & 1;                   // B ldmatrix k-chunk

    const uint32_t aHi = sb + SM_AHI,  aLo = sb + SM_ALO;
    const uint32_t w1Hi = sb + SM_W1HI, w1Lo = sb + SM_W1LO;
    const uint32_t cbHi = sb + SM_CBHI, cbLo = sb + SM_CBLO;
    const float* sMz  = (const float*)(smem + SM_MZ);
    const float* sW2g = (const float*)(smem + SM_W2G);
    const float* sB1  = (const float*)(smem + SM_B1);
    const float* sSg  = (const float*)(smem + SM_SG);
    const float* sCq  = (const float*)(smem + SM_CQ);
    const float* sBc  = (const float*)(smem + SM_BC);

    const int gw = blockIdx.x * 4 + w;
    const int nW = gridDim.x * 4;

    for (int s = gw; s < nSlices; s += nW) {
        __syncwarp();
        // ---- stage 32 samples into this warp's private A band (rows 32w..32w+31) ----
        const float4* xg = (const float4*)(x + (size_t)s * 32 * DIM);
        #pragma unroll
        for (int m = 0; m < 16; m++) {
            int idx = m * 32 + l;                // 512 float4
            float4 v = xg[idx];
            int rl = idx >> 4, cg = idx & 15;
            int swb = SW128((32 * w + rl) * 128 + cg * 8);
            __nv_bfloat16 h0 = __float2bfloat16(v.x), h1 = __float2bfloat16(v.y);
            __nv_bfloat16 h2 = __float2bfloat16(v.z), h3 = __float2bfloat16(v.w);
            __nv_bfloat16 l0 = __float2bfloat16(v.x - __bfloat162float(h0));
            __nv_bfloat16 l1 = __float2bfloat16(v.y - __bfloat162float(h1));
            __nv_bfloat16 l2 = __float2bfloat16(v.z - __bfloat162float(h2));
            __nv_bfloat16 l3 = __float2bfloat16(v.w - __bfloat162float(h3));
            uint2 uh, ul;
            uh.x = (uint32_t)__bfloat16_as_ushort(h0) | ((uint32_t)__bfloat16_as_ushort(h1) << 16);
            uh.y = (uint32_t)__bfloat16_as_ushort(h2) | ((uint32_t)__bfloat16_as_ushort(h3) << 16);
            ul.x = (uint32_t)__bfloat16_as_ushort(l0) | ((uint32_t)__bfloat16_as_ushort(l1) << 16);
            ul.y = (uint32_t)__bfloat16_as_ushort(l2) | ((uint32_t)__bfloat16_as_ushort(l3) << 16);
            *(uint2*)(smem + SM_AHI + swb) = uh;
            *(uint2*)(smem + SM_ALO + swb) = ul;
        }
        __syncwarp();

        // ---- GEMM1: D1[32,64] = X @ W1^T, 3-term bf16 split ----
        float d1[2][8][4];
        #pragma unroll
        for (int mb = 0; mb < 2; mb++)
            #pragma unroll
            for (int nb = 0; nb < 8; nb++)
                #pragma unroll
                for (int c = 0; c < 4; c++) d1[mb][nb][c] = 0.f;

        #pragma unroll
        for (int k = 0; k < 4; k++) {
            uint32_t Ah[2][4], Al[2][4];
            #pragma unroll
            for (int mb = 0; mb < 2; mb++) {
                int sw = SW128((32*w + 16*mb + a_r) * 128 + (k*2 + a_k) * 16);
                LDMX4(Ah[mb], aHi + sw);
                LDMX4(Al[mb], aLo + sw);
            }
            uint32_t Bh[4][4], Bl[4][4];
            #pragma unroll
            for (int np = 0; np < 4; np++) {
                int sw = SW128((np*16 + b_r) * 128 + (k*2 + b_k) * 16);
                LDMX4(Bh[np], w1Hi + sw);
                LDMX4(Bl[np], w1Lo + sw);
            }
            #pragma unroll
            for (int np = 0; np < 4; np++)
                #pragma unroll
                for (int mb = 0; mb < 2; mb++) {
                    mma_bf16(d1[mb][2*np],   Ah[mb], Bh[np][0], Bh[np][1]);
                    mma_bf16(d1[mb][2*np+1], Ah[mb], Bh[np][2], Bh[np][3]);
                }
            #pragma unroll
            for (int np = 0; np < 4; np++)
                #pragma unroll
                for (int mb = 0; mb < 2; mb++) {
                    mma_bf16(d1[mb][2*np],   Ah[mb], Bl[np][0], Bl[np][1]);
                    mma_bf16(d1[mb][2*np+1], Ah[mb], Bl[np][2], Bl[np][3]);
                }
            #pragma unroll
            for (int np = 0; np < 4; np++)
                #pragma unroll
                for (int mb = 0; mb < 2; mb++) {
                    mma_bf16(d1[mb][2*np],   Al[mb], Bh[np][0], Bh[np][1]);
                    mma_bf16(d1[mb][2*np+1], Al[mb], Bh[np][2], Bh[np][3]);
                }
        }

        // ---- epilogue1: bias+relu, LN stats + z-dots (quad-shared rows) ----
        float h[4][16];   // [ri][2*nb+ci]; ri = mb*2+ch -> row = 16mb+8ch+lg
        #pragma unroll
        for (int nb = 0; nb < 8; nb++) {
            float2 bb = *(const float2*)(sB1 + nb*8 + lq*2);
            #pragma unroll
            for (int mb = 0; mb < 2; mb++) {
                h[mb*2+0][2*nb+0] = fmaxf(d1[mb][nb][0] + bb.x, 0.f);
                h[mb*2+0][2*nb+1] = fmaxf(d1[mb][nb][1] + bb.y, 0.f);
                h[mb*2+1][2*nb+0] = fmaxf(d1[mb][nb][2] + bb.x, 0.f);
                h[mb*2+1][2*nb+1] = fmaxf(d1[mb][nb][3] + bb.y, 0.f);
            }
        }
        float su[4] = {0,0,0,0}, sq[4] = {0,0,0,0}, dq[4][NQ];
        #pragma unroll
        for (int ri = 0; ri < 4; ri++)
            #pragma unroll
            for (int q = 0; q < NQ; q++) dq[ri][q] = 0.f;
        #pragma unroll
        for (int nb = 0; nb < 8; nb++) {
            const float* w0 = sW2g + (nb*8 + lq*2) * 8;
            float4 wa0 = *(const float4*)(w0);
            float2 wb0 = *(const float2*)(w0 + 4);
            float4 wa1 = *(const float4*)(w0 + 8);
            float2 wb1 = *(const float2*)(w0 + 12);
            #pragma unroll
            for (int ri = 0; ri < 4; ri++) {
                float h0 = h[ri][2*nb], h1 = h[ri][2*nb+1];
                su[ri] += h0 + h1;
                sq[ri] += h0*h0 + h1*h1;
                dq[ri][0] += h0*wa0.x + h1*wa1.x;
                dq[ri][1] += h0*wa0.y + h1*wa1.y;
                dq[ri][2] += h0*wa0.z + h1*wa1.z;
                dq[ri][3] += h0*wa0.w + h1*wa1.w;
                dq[ri][4] += h0*wb0.x + h1*wb1.x;
                dq[ri][5] += h0*wb0.y + h1*wb1.y;
            }
        }
        #pragma unroll
        for (int off = 1; off <= 2; off <<= 1)
            #pragma unroll
            for (int ri = 0; ri < 4; ri++) {
                su[ri] += __shfl_xor_sync(0xffffffffu, su[ri], off);
                sq[ri] += __shfl_xor_sync(0xffffffffu, sq[ri], off);
                #pragma unroll
                for (int q = 0; q < NQ; q++)
                    dq[ri][q] += __shfl_xor_sync(0xffffffffu, dq[ri][q], off);
            }

        // lane owns row ri = lq  (row = 16*(lq>>1) + 8*(lq&1) + lg = 8*lq + lg)
        float vecv[12];
        {
            float S = su[lq], Q = sq[lq];
            float mu  = S * (1.f / DIM);
            float var = Q * (1.f / DIM) - mu * mu;
            float inv = rsqrtf(var + 1e-5f);
            #pragma unroll
            for (int q = 0; q < NQ; q++) {
                float z  = fast_tanh(inv * (dq[lq][q] - mu * sSg[q]) + sCq[q]);
                float hh = 1.5707963267948966f * z;
                float sn, cs;
                __sincosf(hh, &sn, &cs);
                vecv[2*q] = cs; vecv[2*q+1] = sn;
            }
        }
        // psi0 tree
        float p6[64];
        {
            float t2[2], t4[4], t8[8], t16[16], t32[32];
            t2[0] = vecv[0]; t2[1] = vecv[1];
            #pragma unroll
            for (int k = 0; k < 2; k++)  { t4[2*k] = t2[k]*vecv[2];  t4[2*k+1] = t2[k]*vecv[3]; }
            #pragma unroll
            for (int k = 0; k < 4; k++)  { t8[2*k] = t4[k]*vecv[4];  t8[2*k+1] = t4[k]*vecv[5]; }
            #pragma unroll
            for (int k = 0; k < 8; k++)  { t16[2*k] = t8[k]*vecv[6]; t16[2*k+1] = t8[k]*vecv[7]; }
            #pragma unroll
            for (int k = 0; k < 16; k++) { t32[2*k] = t16[k]*vecv[8]; t32[2*k+1] = t16[k]*vecv[9]; }
            #pragma unroll
            for (int k = 0; k < 32; k++) { p6[2*k] = t32[k]*vecv[10]; p6[2*k+1] = t32[k]*vecv[11]; }
        }
        // store psi (bf16 split) into this lane's row, lane-rotated chunks
        {
            int r = 32 * w + rowLoc;
            #pragma unroll
            for (int cg0 = 0; cg0 < 16; cg0++) {
                int cg = (cg0 + l) & 15;
                float v0 = p6[cg*4+0], v1 = p6[cg*4+1], v2 = p6[cg*4+2], v3 = p6[cg*4+3];
                __nv_bfloat16 h0 = __float2bfloat16(v0), h1 = __float2bfloat16(v1);
                __nv_bfloat16 h2 = __float2bfloat16(v2), h3 = __float2bfloat16(v3);
                __nv_bfloat16 l0 = __float2bfloat16(v0 - __bfloat162float(h0));
                __nv_bfloat16 l1 = __float2bfloat16(v1 - __bfloat162float(h1));
                __nv_bfloat16 l2 = __float2bfloat16(v2 - __bfloat162float(h2));
                __nv_bfloat16 l3 = __float2bfloat16(v3 - __bfloat162float(h3));
                uint2 uh, ul;
                uh.x = (uint32_t)__bfloat16_as_ushort(h0) | ((uint32_t)__bfloat16_as_ushort(h1) << 16);
                uh.y = (uint32_t)__bfloat16_as_ushort(h2) | ((uint32_t)__bfloat16_as_ushort(h3) << 16);
                ul.x = (uint32_t)__bfloat16_as_ushort(l0) | ((uint32_t)__bfloat16_as_ushort(l1) << 16);
                ul.y = (uint32_t)__bfloat16_as_ushort(l2) | ((uint32_t)__bfloat16_as_ushort(l3) << 16);
                int swb = SW128(r * 128 + cg * 8);
                *(uint2*)(smem + SM_AHI + swb) = uh;
                *(uint2*)(smem + SM_ALO + swb) = ul;
            }
        }
        __syncwarp();

        // ---- GEMM2/3: D2[32,128] = psi @ [CR;CI]^T ----
        float d2[2][16][4];
        #pragma unroll
        for (int mb = 0; mb < 2; mb++)
            #pragma unroll
            for (int nb = 0; nb < 16; nb++)
                #pragma unroll
                for (int c = 0; c < 4; c++) d2[mb][nb][c] = 0.f;

        #pragma unroll
        for (int k = 0; k < 4; k++) {
            uint32_t Ah[2][4], Al[2][4];
            #pragma unroll
            for (int mb = 0; mb < 2; mb++) {
                int sw = SW128((32*w + 16*mb + a_r) * 128 + (k*2 + a_k) * 16);
                LDMX4(Ah[mb], aHi + sw);
                LDMX4(Al[mb], aLo + sw);
            }
            #pragma unroll
            for (int g2 = 0; g2 < 2; g2++) {
                uint32_t Bh[4][4], Bl[4][4];
                #pragma unroll
                for (int np = 0; np < 4; np++) {
                    int sw = SW128(((g2*4 + np)*16 + b_r) * 128 + (k*2 + b_k) * 16);
                    LDMX4(Bh[np], cbHi + sw);
                    LDMX4(Bl[np], cbLo + sw);
                }
                #pragma unroll
                for (int np = 0; np < 4; np++)
                    #pragma unroll
                    for (int mb = 0; mb < 2; mb++) {
                        mma_bf16(d2[mb][g2*8 + 2*np],   Ah[mb], Bh[np][0], Bh[np][1]);
                        mma_bf16(d2[mb][g2*8 + 2*np+1], Ah[mb], Bh[np][2], Bh[np][3]);
                    }
                #pragma unroll
                for (int np = 0; np < 4; np++)
                    #pragma unroll
                    for (int mb = 0; mb < 2; mb++) {
                        mma_bf16(d2[mb][g2*8 + 2*np],   Ah[mb], Bl[np][0], Bl[np][1]);
                        mma_bf16(d2[mb][g2*8 + 2*np+1], Ah[mb], Bl[np][2], Bl[np][3]);
                    }
                #pragma unroll
                for (int np = 0; np < 4; np++)
                    #pragma unroll
                    for (int mb = 0; mb < 2; mb++) {
                        mma_bf16(d2[mb][g2*8 + 2*np],   Al[mb], Bh[np][0], Bh[np][1]);
                        mma_bf16(d2[mb][g2*8 + 2*np+1], Al[mb], Bh[np][2], Bh[np][3]);
                    }
            }
        }

        // ---- epilogue2: probs = R^2 + I^2 -> Mz dot -> reduce -> out ----
        float acc[4][5];
        #pragma unroll
        for (int ri = 0; ri < 4; ri++)
            #pragma unroll
            for (int o = 0; o < 5; o++) acc[ri][o] = 0.f;
        #pragma unroll
        for (int nb = 0; nb < 8; nb++) {
            const float* mzp = sMz + (nb*8 + lq*2) * 8;
            float4 ma0 = *(const float4*)(mzp);
            float  m40 = mzp[4];
            float4 ma1 = *(const float4*)(mzp + 8);
            float  m41 = mzp[12];
            #pragma unroll
            for (int mb = 0; mb < 2; mb++)
                #pragma unroll
                for (int ch = 0; ch < 2; ch++) {
                    int ri = mb*2 + ch;
                    float R0 = d2[mb][nb][ch*2+0],   R1 = d2[mb][nb][ch*2+1];
                    float I0 = d2[mb][nb+8][ch*2+0], I1 = d2[mb][nb+8][ch*2+1];
                    float p0 = R0*R0 + I0*I0;
                    float p1 = R1*R1 + I1*I1;
                    acc[ri][0] += p0*ma0.x + p1*ma1.x;
                    acc[ri][1] += p0*ma0.y + p1*ma1.y;
                    acc[ri][2] += p0*ma0.z + p1*ma1.z;
                    acc[ri][3] += p0*ma0.w + p1*ma1.w;
                    acc[ri][4] += p0*m40  + p1*m41;
                }
        }
        #pragma unroll
        for (int off = 1; off <= 2; off <<= 1)
            #pragma unroll
            for (int ri = 0; ri < 4; ri++)
                #pragma unroll
                for (int o = 0; o < 5; o++)
                    acc[ri][o] += __shfl_xor_sync(0xffffffffu, acc[ri][o], off);

        float* og = out + ((size_t)s * 32 + rowLoc) * 5;
        og[0] = acc[lq][0] + sBc[0];
        og[1] = acc[lq][1] + sBc[1];
        og[2] = acc[lq][2] + sBc[2];
        og[3] = acc[lq][3] + sBc[3];
        og[4] = acc[lq][4] + sBc[4];
    }
}

extern "C" void kernel_launch(void* const* d_in, const int* in_sizes, int n_in,
                              void* d_out, int out_size) {
    const float* x     = (const float*)d_in[0];
    const float* W1    = (const float*)d_in[1];
    const float* b1    = (const float*)d_in[2];
    const float* ln_g  = (const float*)d_in[3];
    const float* ln_b  = (const float*)d_in[4];
    const float* W2    = (const float*)d_in[5];
    const float* b2    = (const float*)d_in[6];
    const float* th_sh = (const float*)d_in[7];
    const float* th_tk = (const float*)d_in[8];
    const float* Wc    = (const float*)d_in[9];
    const float* bc    = (const float*)d_in[10];
    float* out = (float*)d_out;

    int B = in_sizes[0] / DIM;
    int nSlices = B / 32;            // 4096

    setup_kernel<<<1, 1024>>>(th_sh, th_tk, Wc, W2, ln_g, ln_b, b2, W1);

    cudaFuncSetAttribute(qmaml_mma_kernel,
                         cudaFuncAttributeMaxDynamicSharedMemorySize, SMEM_SZ);
    int grid = 304;                  // 2 CTAs x 152 SMs
    qmaml_mma_kernel<<<grid, 128, SMEM_SZ>>>(x, b1, bc, out, nSlices);
}